// round 1
// baseline (speedup 1.0000x reference)
#include <cuda_runtime.h>
#include <cuda_bf16.h>
#include <math.h>

// Problem constants (fixed by the reference)
#define NN 50000
#define EE 400000
#define FF 128
#define INV_SCALE 0.17677669529663687f   // 1/sqrt(32)
#define LN_EPS 1e-5f

// Scratch: q, k, v, node_res, agg  (5 * N * 128)  then eproj, eres (2 * E * 128)
// total = (5*50000 + 2*400000) * 128 = 134,400,000 floats (~537 MB)
__device__ float g_scratch[134400000];

// ---------------------------------------------------------------------------
// GEMM: Y[m, n] = sum_k X[m, k] * W[n, k] + b[n]   (K = N = 128 fixed)
// 128x128 block tile, BK=16, 256 threads, 8x8 register blocking.
// ---------------------------------------------------------------------------
__global__ __launch_bounds__(256) void gemm128(
    const float* __restrict__ X, const float* __restrict__ W,
    const float* __restrict__ b, float* __restrict__ Y, int M)
{
    __shared__ float Xs[16][132];
    __shared__ float Ws[16][132];

    const int block_m = blockIdx.x * 128;
    const int tid = threadIdx.x;
    const int tr = tid >> 4;   // 0..15
    const int tc = tid & 15;   // 0..15

    float acc[8][8];
    #pragma unroll
    for (int i = 0; i < 8; i++)
        #pragma unroll
        for (int j = 0; j < 8; j++) acc[i][j] = 0.0f;

    #pragma unroll
    for (int k0 = 0; k0 < 128; k0 += 16) {
        // Load X tile [128 rows x 16 k] -> Xs[k][m]
        #pragma unroll
        for (int it = 0; it < 2; it++) {
            int idx = tid + it * 256;          // 0..511
            int row = idx >> 2;                // 0..127
            int cv  = idx & 3;                 // float4 index in 16
            int gm  = block_m + row;
            float4 xv = make_float4(0.f, 0.f, 0.f, 0.f);
            if (gm < M)
                xv = *reinterpret_cast<const float4*>(&X[(size_t)gm * 128 + k0 + cv * 4]);
            Xs[cv * 4 + 0][row] = xv.x;
            Xs[cv * 4 + 1][row] = xv.y;
            Xs[cv * 4 + 2][row] = xv.z;
            Xs[cv * 4 + 3][row] = xv.w;
        }
        // Load W tile: Ws[k][n] = W[n][k0+k]
        #pragma unroll
        for (int it = 0; it < 2; it++) {
            int idx = tid + it * 256;
            int n  = idx >> 2;
            int cv = idx & 3;
            float4 wv = *reinterpret_cast<const float4*>(&W[(size_t)n * 128 + k0 + cv * 4]);
            Ws[cv * 4 + 0][n] = wv.x;
            Ws[cv * 4 + 1][n] = wv.y;
            Ws[cv * 4 + 2][n] = wv.z;
            Ws[cv * 4 + 3][n] = wv.w;
        }
        __syncthreads();

        #pragma unroll
        for (int kk = 0; kk < 16; kk++) {
            float am[8], bn[8];
            #pragma unroll
            for (int i = 0; i < 8; i++) am[i] = Xs[kk][tr * 8 + i];
            #pragma unroll
            for (int j = 0; j < 8; j++) bn[j] = Ws[kk][tc * 8 + j];
            #pragma unroll
            for (int i = 0; i < 8; i++)
                #pragma unroll
                for (int j = 0; j < 8; j++)
                    acc[i][j] = fmaf(am[i], bn[j], acc[i][j]);
        }
        __syncthreads();
    }

    // Epilogue: add bias, store
    #pragma unroll
    for (int i = 0; i < 8; i++) {
        int gm = block_m + tr * 8 + i;
        if (gm < M) {
            #pragma unroll
            for (int j = 0; j < 8; j += 4) {
                int n = tc * 8 + j;
                float4 o;
                o.x = acc[i][j + 0] + b[n + 0];
                o.y = acc[i][j + 1] + b[n + 1];
                o.z = acc[i][j + 2] + b[n + 2];
                o.w = acc[i][j + 3] + b[n + 3];
                *reinterpret_cast<float4*>(&Y[(size_t)gm * 128 + n]) = o;
            }
        }
    }
}

// ---------------------------------------------------------------------------
// Zero agg buffer
// ---------------------------------------------------------------------------
__global__ void zero_kernel(float* __restrict__ p, int n4)
{
    int i = blockIdx.x * blockDim.x + threadIdx.x;
    if (i < n4) reinterpret_cast<float4*>(p)[i] = make_float4(0.f, 0.f, 0.f, 0.f);
}

// ---------------------------------------------------------------------------
// Edge kernel: one warp per edge.
// lane handles column c = lane for all 4 heads (flat index h*32 + lane).
//  score[h] = sum_c q[src][h,c]*k[dst][h,c]
//  m[h]     = score[h]/SCALE + eproj[h,c]
//  attn     = softmax over h (per c)
//  atomicAdd(agg[dst][h,c], v[src][h,c]*attn[h])
//  y        = silu(LN_128(m)) + eres
// ---------------------------------------------------------------------------
__global__ __launch_bounds__(256) void edge_kernel(
    const int* __restrict__ src, const int* __restrict__ dst,
    const float* __restrict__ q, const float* __restrict__ k,
    const float* __restrict__ v,
    const float* __restrict__ eproj, const float* __restrict__ eres,
    const float* __restrict__ ln_eg, const float* __restrict__ ln_eb,
    float* __restrict__ agg, float* __restrict__ y_out)
{
    int warp = (blockIdx.x * blockDim.x + threadIdx.x) >> 5;
    int lane = threadIdx.x & 31;
    if (warp >= EE) return;

    int s = src[warp];
    int d = dst[warp];
    size_t sbase = (size_t)s * 128 + lane;
    size_t dbase = (size_t)d * 128 + lane;
    size_t ebase = (size_t)warp * 128 + lane;

    float dotp[4], vv[4], m[4];
    #pragma unroll
    for (int h = 0; h < 4; h++) {
        float qv = q[sbase + h * 32];
        float kv = k[dbase + h * 32];
        dotp[h] = qv * kv;
        vv[h]   = v[sbase + h * 32];
    }
    // warp-reduce the 4 head dots
    #pragma unroll
    for (int off = 16; off > 0; off >>= 1) {
        #pragma unroll
        for (int h = 0; h < 4; h++)
            dotp[h] += __shfl_xor_sync(0xffffffffu, dotp[h], off);
    }
    #pragma unroll
    for (int h = 0; h < 4; h++)
        m[h] = fmaf(dotp[h], INV_SCALE, eproj[ebase + h * 32]);

    // softmax over the 4 heads (per column c = lane)
    float mx = fmaxf(fmaxf(m[0], m[1]), fmaxf(m[2], m[3]));
    float ex[4];
    float se = 0.f;
    #pragma unroll
    for (int h = 0; h < 4; h++) { ex[h] = __expf(m[h] - mx); se += ex[h]; }
    float inv_se = 1.0f / se;

    // scatter-add messages
    #pragma unroll
    for (int h = 0; h < 4; h++)
        atomicAdd(&agg[dbase + h * 32], vv[h] * ex[h] * inv_se);

    // layernorm over the 128 m values (warp holds all of them: 4 per lane)
    float ssum = m[0] + m[1] + m[2] + m[3];
    float ssq  = m[0]*m[0] + m[1]*m[1] + m[2]*m[2] + m[3]*m[3];
    #pragma unroll
    for (int off = 16; off > 0; off >>= 1) {
        ssum += __shfl_xor_sync(0xffffffffu, ssum, off);
        ssq  += __shfl_xor_sync(0xffffffffu, ssq,  off);
    }
    float mu  = ssum * (1.0f / 128.0f);
    float var = ssq * (1.0f / 128.0f) - mu * mu;
    float rs  = rsqrtf(var + LN_EPS);

    #pragma unroll
    for (int h = 0; h < 4; h++) {
        float g = ln_eg[h * 32 + lane];
        float bb = ln_eb[h * 32 + lane];
        float t = fmaf((m[h] - mu) * rs, g, bb);
        float sil = t / (1.0f + __expf(-t));
        y_out[ebase + h * 32] = sil + eres[ebase + h * 32];
    }
}

// ---------------------------------------------------------------------------
// Node finalize: one warp per node. x = node_res + silu(LN_128(agg))
// ---------------------------------------------------------------------------
__global__ __launch_bounds__(256) void node_kernel(
    const float* __restrict__ agg, const float* __restrict__ nres,
    const float* __restrict__ ln_ng, const float* __restrict__ ln_nb,
    float* __restrict__ x_out)
{
    int warp = (blockIdx.x * blockDim.x + threadIdx.x) >> 5;
    int lane = threadIdx.x & 31;
    if (warp >= NN) return;

    size_t base = (size_t)warp * 128 + lane;
    float a[4];
    #pragma unroll
    for (int h = 0; h < 4; h++) a[h] = agg[base + h * 32];

    float ssum = a[0] + a[1] + a[2] + a[3];
    float ssq  = a[0]*a[0] + a[1]*a[1] + a[2]*a[2] + a[3]*a[3];
    #pragma unroll
    for (int off = 16; off > 0; off >>= 1) {
        ssum += __shfl_xor_sync(0xffffffffu, ssum, off);
        ssq  += __shfl_xor_sync(0xffffffffu, ssq,  off);
    }
    float mu  = ssum * (1.0f / 128.0f);
    float var = ssq * (1.0f / 128.0f) - mu * mu;
    float rs  = rsqrtf(var + LN_EPS);

    #pragma unroll
    for (int h = 0; h < 4; h++) {
        float g = ln_ng[h * 32 + lane];
        float bb = ln_nb[h * 32 + lane];
        float t = fmaf((a[h] - mu) * rs, g, bb);
        float sil = t / (1.0f + __expf(-t));
        x_out[base + h * 32] = sil + nres[base + h * 32];
    }
}

// ---------------------------------------------------------------------------
// Launch
// ---------------------------------------------------------------------------
extern "C" void kernel_launch(void* const* d_in, const int* in_sizes, int n_in,
                              void* d_out, int out_size)
{
    const float* node_feats = (const float*)d_in[0];
    const float* edge_feats = (const float*)d_in[1];
    const int*   src        = (const int*)d_in[2];
    const int*   dst        = (const int*)d_in[3];
    const float* Wq   = (const float*)d_in[4];
    const float* bq   = (const float*)d_in[5];
    const float* Wk   = (const float*)d_in[6];
    const float* bk   = (const float*)d_in[7];
    const float* Wv   = (const float*)d_in[8];
    const float* bv   = (const float*)d_in[9];
    const float* We   = (const float*)d_in[10];
    const float* be   = (const float*)d_in[11];
    const float* Wev  = (const float*)d_in[12];
    const float* bev  = (const float*)d_in[13];
    const float* Wout = (const float*)d_in[14];
    const float* bout = (const float*)d_in[15];
    const float* ln_ng = (const float*)d_in[16];
    const float* ln_nb = (const float*)d_in[17];
    const float* ln_eg = (const float*)d_in[18];
    const float* ln_eb = (const float*)d_in[19];

    float* scratch = nullptr;
    cudaGetSymbolAddress((void**)&scratch, g_scratch);
    float* q     = scratch;
    float* kk    = q    + (size_t)NN * 128;
    float* vv    = kk   + (size_t)NN * 128;
    float* nres  = vv   + (size_t)NN * 128;
    float* agg   = nres + (size_t)NN * 128;
    float* eproj = agg  + (size_t)NN * 128;
    float* eres  = eproj + (size_t)EE * 128;

    float* x_out = (float*)d_out;                  // [N, 128]
    float* y_out = x_out + (size_t)NN * 128;       // [E, 128]

    const int node_blocks = (NN + 127) / 128;      // 391
    const int edge_blocks = (EE + 127) / 128;      // 3125

    gemm128<<<node_blocks, 256>>>(node_feats, Wq,   bq,   q,     NN);
    gemm128<<<node_blocks, 256>>>(node_feats, Wk,   bk,   kk,    NN);
    gemm128<<<node_blocks, 256>>>(node_feats, Wv,   bv,   vv,    NN);
    gemm128<<<node_blocks, 256>>>(node_feats, Wout, bout, nres,  NN);
    gemm128<<<edge_blocks, 256>>>(edge_feats, We,   be,   eproj, EE);
    gemm128<<<edge_blocks, 256>>>(edge_feats, Wev,  bev,  eres,  EE);

    // zero the aggregation buffer (float4-wide)
    int n4 = NN * 128 / 4;
    zero_kernel<<<(n4 + 255) / 256, 256>>>(agg, n4);

    // one warp per edge: 400000 warps = 50000 blocks of 8 warps
    edge_kernel<<<EE / 8, 256>>>(src, dst, q, kk, vv, eproj, eres,
                                 ln_eg, ln_eb, agg, y_out);

    // one warp per node: 50000 warps = 6250 blocks of 8 warps
    node_kernel<<<NN / 8, 256>>>(agg, nres, ln_ng, ln_nb, x_out);
}

// round 2
// speedup vs baseline: 1.6530x; 1.6530x over previous
#include <cuda_runtime.h>
#include <cuda_bf16.h>
#include <math.h>

#define NN 50000
#define EE 400000
#define INV_SCALE 0.17677669529663687f   // 1/sqrt(32)
#define LN_EPS 1e-5f

// Scratch: q, k, v, node_res, agg  (5 * N * 128 = 32,000,000 floats, 128 MB)
__device__ float g_scratch[32000000];

typedef unsigned long long u64;

// ---------------------------------------------------------------------------
// f32x2 packed helpers (sm_103a FFMA2 — only reachable via PTX)
// ---------------------------------------------------------------------------
__device__ __forceinline__ u64 ffma2(u64 a, u64 b, u64 c) {
    u64 d;
    asm("fma.rn.f32x2 %0, %1, %2, %3;" : "=l"(d) : "l"(a), "l"(b), "l"(c));
    return d;
}
__device__ __forceinline__ u64 pack2(float x) {
    u64 r;
    unsigned xi = __float_as_uint(x);
    asm("mov.b64 %0, {%1, %1};" : "=l"(r) : "r"(xi));
    return r;
}
__device__ __forceinline__ float2 unpack2(u64 p) {
    unsigned lo, hi;
    asm("mov.b64 {%0, %1}, %2;" : "=r"(lo), "=r"(hi) : "l"(p));
    return make_float2(__uint_as_float(lo), __uint_as_float(hi));
}

// ---------------------------------------------------------------------------
// GEMM core: acc[i][g] covers rows tr*8+i, column pairs n = 32g + 2tc + {0,1}.
// Computes Xblk[128,128] @ W[128,128]^T into acc (f32x2 packed along n).
// xs/ws: [16][132] smem tiles. Register-staged double buffering on global.
// ---------------------------------------------------------------------------
__device__ __forceinline__ void gemm_core(
    const float* __restrict__ Xblk, const float* __restrict__ W,
    float (*xs)[132], float (*ws)[132],
    u64 acc[8][4], int rows_valid)
{
    const int tid  = threadIdx.x;
    const int tr   = tid >> 4;
    const int tc   = tid & 15;
    const int lrow = tid >> 2;   // 0..63
    const int lcv  = tid & 3;

    #pragma unroll
    for (int i = 0; i < 8; i++)
        #pragma unroll
        for (int g = 0; g < 4; g++) acc[i][g] = 0ull;

    float4 xr[2], wr[2];
    // prefetch k0 = 0
    #pragma unroll
    for (int it = 0; it < 2; it++) {
        int row = lrow + it * 64;
        xr[it] = (row < rows_valid)
                   ? *reinterpret_cast<const float4*>(&Xblk[(size_t)row * 128 + lcv * 4])
                   : make_float4(0.f, 0.f, 0.f, 0.f);
        wr[it] = *reinterpret_cast<const float4*>(&W[(size_t)row * 128 + lcv * 4]);
    }

    #pragma unroll
    for (int t = 0; t < 8; t++) {
        // stage current tile into smem (transposed: [k][m] / [k][n])
        #pragma unroll
        for (int it = 0; it < 2; it++) {
            int row = lrow + it * 64;
            xs[lcv * 4 + 0][row] = xr[it].x;
            xs[lcv * 4 + 1][row] = xr[it].y;
            xs[lcv * 4 + 2][row] = xr[it].z;
            xs[lcv * 4 + 3][row] = xr[it].w;
            ws[lcv * 4 + 0][row] = wr[it].x;
            ws[lcv * 4 + 1][row] = wr[it].y;
            ws[lcv * 4 + 2][row] = wr[it].z;
            ws[lcv * 4 + 3][row] = wr[it].w;
        }
        __syncthreads();

        // prefetch next tile while computing (hides global latency)
        float4 xn[2], wn[2];
        if (t < 7) {
            int k0 = (t + 1) * 16;
            #pragma unroll
            for (int it = 0; it < 2; it++) {
                int row = lrow + it * 64;
                xn[it] = (row < rows_valid)
                           ? *reinterpret_cast<const float4*>(&Xblk[(size_t)row * 128 + k0 + lcv * 4])
                           : make_float4(0.f, 0.f, 0.f, 0.f);
                wn[it] = *reinterpret_cast<const float4*>(&W[(size_t)row * 128 + k0 + lcv * 4]);
            }
        }

        #pragma unroll
        for (int kk = 0; kk < 16; kk++) {
            float4 a0 = *reinterpret_cast<const float4*>(&xs[kk][tr * 8]);
            float4 a1 = *reinterpret_cast<const float4*>(&xs[kk][tr * 8 + 4]);
            u64 bn[4];
            #pragma unroll
            for (int g = 0; g < 4; g++)
                bn[g] = *reinterpret_cast<const u64*>(&ws[kk][32 * g + 2 * tc]);
            u64 am[8];
            am[0] = pack2(a0.x); am[1] = pack2(a0.y);
            am[2] = pack2(a0.z); am[3] = pack2(a0.w);
            am[4] = pack2(a1.x); am[5] = pack2(a1.y);
            am[6] = pack2(a1.z); am[7] = pack2(a1.w);
            #pragma unroll
            for (int i = 0; i < 8; i++)
                #pragma unroll
                for (int g = 0; g < 4; g++)
                    acc[i][g] = ffma2(am[i], bn[g], acc[i][g]);
        }
        __syncthreads();

        if (t < 7) {
            #pragma unroll
            for (int it = 0; it < 2; it++) { xr[it] = xn[it]; wr[it] = wn[it]; }
        }
    }
}

// ---------------------------------------------------------------------------
// Node-side GEMM: Y = X @ W^T + b
// ---------------------------------------------------------------------------
__global__ __launch_bounds__(256) void gemm128_v2(
    const float* __restrict__ X, const float* __restrict__ W,
    const float* __restrict__ b, float* __restrict__ Y, int M)
{
    __shared__ float xs[16][132];
    __shared__ float ws[16][132];
    const int bm = blockIdx.x * 128;
    const int rows_valid = min(128, M - bm);

    u64 acc[8][4];
    gemm_core(X + (size_t)bm * 128, W, xs, ws, acc, rows_valid);

    const int tr = threadIdx.x >> 4;
    const int tc = threadIdx.x & 15;
    float2 bb[4];
    #pragma unroll
    for (int g = 0; g < 4; g++)
        bb[g] = *reinterpret_cast<const float2*>(&b[32 * g + 2 * tc]);

    #pragma unroll
    for (int i = 0; i < 8; i++) {
        int row = tr * 8 + i;
        if (row < rows_valid) {
            #pragma unroll
            for (int g = 0; g < 4; g++) {
                float2 p = unpack2(acc[i][g]);
                p.x += bb[g].x; p.y += bb[g].y;
                *reinterpret_cast<float2*>(&Y[(size_t)(bm + row) * 128 + 32 * g + 2 * tc]) = p;
            }
        }
    }
}

// ---------------------------------------------------------------------------
// Fused edge kernel: block = 128 edges.
//   Phase A: P = edge_feats @ We^T + be           (in smem)
//   Phase B: score/softmax-over-heads/atomic agg; P <- silu(LN(m))
//   Phase C: y = edge_feats @ Wev^T + bev + P
// ---------------------------------------------------------------------------
__global__ __launch_bounds__(256) void edge_fused(
    const float* __restrict__ edge_feats,
    const float* __restrict__ We,  const float* __restrict__ be,
    const float* __restrict__ Wev, const float* __restrict__ bev,
    const int* __restrict__ src, const int* __restrict__ dst,
    const float* __restrict__ q, const float* __restrict__ k,
    const float* __restrict__ v,
    const float* __restrict__ ln_eg, const float* __restrict__ ln_eb,
    float* __restrict__ agg, float* __restrict__ y_out)
{
    extern __shared__ float smem[];
    float (*xs)[132] = reinterpret_cast<float(*)[132]>(smem);
    float (*ws)[132] = reinterpret_cast<float(*)[132]>(smem + 16 * 132);
    float (*P)[132]  = reinterpret_cast<float(*)[132]>(smem + 32 * 132);

    const int e0  = blockIdx.x * 128;
    const int tid = threadIdx.x;
    const int tr  = tid >> 4;
    const int tc  = tid & 15;

    u64 acc[8][4];

    // ---- Phase A: eproj GEMM -> P ----
    gemm_core(edge_feats + (size_t)e0 * 128, We, xs, ws, acc, 128);
    {
        float2 bb[4];
        #pragma unroll
        for (int g = 0; g < 4; g++)
            bb[g] = *reinterpret_cast<const float2*>(&be[32 * g + 2 * tc]);
        #pragma unroll
        for (int i = 0; i < 8; i++) {
            int row = tr * 8 + i;
            #pragma unroll
            for (int g = 0; g < 4; g++) {
                float2 p = unpack2(acc[i][g]);
                P[row][32 * g + 2 * tc]     = p.x + bb[g].x;
                P[row][32 * g + 2 * tc + 1] = p.y + bb[g].y;
            }
        }
    }
    __syncthreads();

    // ---- Phase B: per-edge attention math (warp per edge, 16 edges/warp) ----
    {
        const int warp = tid >> 5;
        const int lane = tid & 31;
        const unsigned FULL = 0xffffffffu;
        const int rbase = warp * 16;

        // preload 16 src (lanes 0-15) and 16 dst (lanes 16-31) indices
        int eidx = e0 + rbase + (lane & 15);
        int sd = (lane < 16) ? __ldg(&src[eidx]) : __ldg(&dst[eidx]);

        float eg[4], eb[4];
        #pragma unroll
        for (int h = 0; h < 4; h++) {
            eg[h] = ln_eg[h * 32 + lane];
            eb[h] = ln_eb[h * 32 + lane];
        }

        int s = __shfl_sync(FULL, sd, 0);
        int d = __shfl_sync(FULL, sd, 16);
        float qv[4], kv[4], vv[4];
        #pragma unroll
        for (int h = 0; h < 4; h++) {
            qv[h] = __ldg(&q[(size_t)s * 128 + h * 32 + lane]);
            kv[h] = __ldg(&k[(size_t)d * 128 + h * 32 + lane]);
            vv[h] = __ldg(&v[(size_t)s * 128 + h * 32 + lane]);
        }

        #pragma unroll 2
        for (int t = 0; t < 16; t++) {
            // prefetch next edge's gathers
            int sn = 0, dn = 0;
            float qn[4], kn[4], vn[4];
            if (t < 15) {
                sn = __shfl_sync(FULL, sd, t + 1);
                dn = __shfl_sync(FULL, sd, t + 17);
                #pragma unroll
                for (int h = 0; h < 4; h++) {
                    qn[h] = __ldg(&q[(size_t)sn * 128 + h * 32 + lane]);
                    kn[h] = __ldg(&k[(size_t)dn * 128 + h * 32 + lane]);
                    vn[h] = __ldg(&v[(size_t)sn * 128 + h * 32 + lane]);
                }
            }

            const int row = rbase + t;
            float dotp[4], m[4];
            #pragma unroll
            for (int h = 0; h < 4; h++) dotp[h] = qv[h] * kv[h];
            #pragma unroll
            for (int off = 16; off > 0; off >>= 1) {
                #pragma unroll
                for (int h = 0; h < 4; h++)
                    dotp[h] += __shfl_xor_sync(FULL, dotp[h], off);
            }
            #pragma unroll
            for (int h = 0; h < 4; h++)
                m[h] = fmaf(dotp[h], INV_SCALE, P[row][h * 32 + lane]);

            // softmax over heads (per column)
            float mx = fmaxf(fmaxf(m[0], m[1]), fmaxf(m[2], m[3]));
            float ex[4], se = 0.f;
            #pragma unroll
            for (int h = 0; h < 4; h++) { ex[h] = __expf(m[h] - mx); se += ex[h]; }
            float inv_se = 1.0f / se;

            #pragma unroll
            for (int h = 0; h < 4; h++)
                atomicAdd(&agg[(size_t)d * 128 + h * 32 + lane], vv[h] * ex[h] * inv_se);

            // layernorm over the 128 m values
            float ssum = m[0] + m[1] + m[2] + m[3];
            float ssq  = m[0]*m[0] + m[1]*m[1] + m[2]*m[2] + m[3]*m[3];
            #pragma unroll
            for (int off = 16; off > 0; off >>= 1) {
                ssum += __shfl_xor_sync(FULL, ssum, off);
                ssq  += __shfl_xor_sync(FULL, ssq,  off);
            }
            float mu  = ssum * (1.0f / 128.0f);
            float var = ssq * (1.0f / 128.0f) - mu * mu;
            float rs  = rsqrtf(var + LN_EPS);

            #pragma unroll
            for (int h = 0; h < 4; h++) {
                float tt = fmaf((m[h] - mu) * rs, eg[h], eb[h]);
                float sil = tt / (1.0f + __expf(-tt));
                P[row][h * 32 + lane] = sil;
            }

            s = sn; d = dn;
            #pragma unroll
            for (int h = 0; h < 4; h++) { qv[h] = qn[h]; kv[h] = kn[h]; vv[h] = vn[h]; }
        }
    }
    __syncthreads();

    // ---- Phase C: eres GEMM + epilogue -> y ----
    gemm_core(edge_feats + (size_t)e0 * 128, Wev, xs, ws, acc, 128);
    {
        float2 bb[4];
        #pragma unroll
        for (int g = 0; g < 4; g++)
            bb[g] = *reinterpret_cast<const float2*>(&bev[32 * g + 2 * tc]);
        #pragma unroll
        for (int i = 0; i < 8; i++) {
            int row = tr * 8 + i;
            #pragma unroll
            for (int g = 0; g < 4; g++) {
                float2 p = unpack2(acc[i][g]);
                int col = 32 * g + 2 * tc;
                float2 o;
                o.x = p.x + bb[g].x + P[row][col];
                o.y = p.y + bb[g].y + P[row][col + 1];
                *reinterpret_cast<float2*>(&y_out[(size_t)(e0 + row) * 128 + col]) = o;
            }
        }
    }
}

// ---------------------------------------------------------------------------
// Zero agg buffer
// ---------------------------------------------------------------------------
__global__ void zero_kernel(float* __restrict__ p, int n4)
{
    int i = blockIdx.x * blockDim.x + threadIdx.x;
    if (i < n4) reinterpret_cast<float4*>(p)[i] = make_float4(0.f, 0.f, 0.f, 0.f);
}

// ---------------------------------------------------------------------------
// Node finalize: x = node_res + silu(LN_128(agg))
// ---------------------------------------------------------------------------
__global__ __launch_bounds__(256) void node_kernel(
    const float* __restrict__ agg, const float* __restrict__ nres,
    const float* __restrict__ ln_ng, const float* __restrict__ ln_nb,
    float* __restrict__ x_out)
{
    int warp = (blockIdx.x * blockDim.x + threadIdx.x) >> 5;
    int lane = threadIdx.x & 31;
    if (warp >= NN) return;

    size_t base = (size_t)warp * 128 + lane;
    float a[4];
    #pragma unroll
    for (int h = 0; h < 4; h++) a[h] = agg[base + h * 32];

    float ssum = a[0] + a[1] + a[2] + a[3];
    float ssq  = a[0]*a[0] + a[1]*a[1] + a[2]*a[2] + a[3]*a[3];
    #pragma unroll
    for (int off = 16; off > 0; off >>= 1) {
        ssum += __shfl_xor_sync(0xffffffffu, ssum, off);
        ssq  += __shfl_xor_sync(0xffffffffu, ssq,  off);
    }
    float mu  = ssum * (1.0f / 128.0f);
    float var = ssq * (1.0f / 128.0f) - mu * mu;
    float rs  = rsqrtf(var + LN_EPS);

    #pragma unroll
    for (int h = 0; h < 4; h++) {
        float g = ln_ng[h * 32 + lane];
        float bb = ln_nb[h * 32 + lane];
        float t = fmaf((a[h] - mu) * rs, g, bb);
        float sil = t / (1.0f + __expf(-t));
        x_out[base + h * 32] = sil + nres[base + h * 32];
    }
}

// ---------------------------------------------------------------------------
// Launch
// ---------------------------------------------------------------------------
extern "C" void kernel_launch(void* const* d_in, const int* in_sizes, int n_in,
                              void* d_out, int out_size)
{
    const float* node_feats = (const float*)d_in[0];
    const float* edge_feats = (const float*)d_in[1];
    const int*   src        = (const int*)d_in[2];
    const int*   dst        = (const int*)d_in[3];
    const float* Wq   = (const float*)d_in[4];
    const float* bq   = (const float*)d_in[5];
    const float* Wk   = (const float*)d_in[6];
    const float* bk   = (const float*)d_in[7];
    const float* Wv   = (const float*)d_in[8];
    const float* bv   = (const float*)d_in[9];
    const float* We   = (const float*)d_in[10];
    const float* be   = (const float*)d_in[11];
    const float* Wev  = (const float*)d_in[12];
    const float* bev  = (const float*)d_in[13];
    const float* Wout = (const float*)d_in[14];
    const float* bout = (const float*)d_in[15];
    const float* ln_ng = (const float*)d_in[16];
    const float* ln_nb = (const float*)d_in[17];
    const float* ln_eg = (const float*)d_in[18];
    const float* ln_eb = (const float*)d_in[19];

    float* scratch = nullptr;
    cudaGetSymbolAddress((void**)&scratch, g_scratch);
    float* q    = scratch;
    float* kk   = q    + (size_t)NN * 128;
    float* vv   = kk   + (size_t)NN * 128;
    float* nres = vv   + (size_t)NN * 128;
    float* agg  = nres + (size_t)NN * 128;

    float* x_out = (float*)d_out;
    float* y_out = x_out + (size_t)NN * 128;

    const int node_blocks = (NN + 127) / 128;   // 391
    const int edge_blocks = EE / 128;           // 3125
    const int EDGE_SMEM = (16 * 132 + 16 * 132 + 128 * 132) * sizeof(float); // 84480

    cudaFuncSetAttribute(edge_fused, cudaFuncAttributeMaxDynamicSharedMemorySize, EDGE_SMEM);

    gemm128_v2<<<node_blocks, 256>>>(node_feats, Wq,   bq,   q,    NN);
    gemm128_v2<<<node_blocks, 256>>>(node_feats, Wk,   bk,   kk,   NN);
    gemm128_v2<<<node_blocks, 256>>>(node_feats, Wv,   bv,   vv,   NN);
    gemm128_v2<<<node_blocks, 256>>>(node_feats, Wout, bout, nres, NN);

    int n4 = NN * 128 / 4;
    zero_kernel<<<(n4 + 255) / 256, 256>>>(agg, n4);

    edge_fused<<<edge_blocks, 256, EDGE_SMEM>>>(
        edge_feats, We, be, Wev, bev, src, dst, q, kk, vv,
        ln_eg, ln_eb, agg, y_out);

    node_kernel<<<NN / 8, 256>>>(agg, nres, ln_ng, ln_nb, x_out);
}

// round 5
// speedup vs baseline: 2.8411x; 1.7188x over previous
#include <cuda_runtime.h>
#include <cuda_bf16.h>
#include <math.h>
#include <stdint.h>

#define NN 50000
#define EE 400000
#define INV_SCALE 0.17677669529663687f   // 1/sqrt(32)
#define LN_EPS 1e-5f

// Scratch: q, k, v, nres, agg (5*N*128 = 32M floats)
__device__ float g_scratch[32000000];
// bf16 hi/lo swizzled weight tiles: 6 weights x (32KB hi + 32KB lo)
__device__ __align__(256) unsigned char g_wbf[6 * 65536];

// ---- smem byte offsets ----
#define SW1HI 0
#define SW1LO 32768
#define SW2HI 65536
#define SW2LO 98304
#define SXHI  131072
#define SXLO  163840
#define SMEM_GEMM 196608
// P (float[128][132]) aliases the X region in the edge kernel
#define SP_OFF 131072
#define SMEM_EDGE (131072 + 128 * 132 * 4)   // 198656

// Swizzled byte offset in a 128x128 bf16 K-major tile (256B rows, 16B chunks,
// chunk ^= row&7 -> conflict-free for both row-parallel and k-parallel access).
__device__ __host__ __forceinline__ int sw_off(int row, int col) {
    return row * 256 + ((((col >> 3) ^ (row & 7)) & 15) << 4) + (col & 7) * 2;
}

__device__ __forceinline__ void hmma(float* c, uint32_t a0, uint32_t a1,
                                     uint32_t a2, uint32_t a3,
                                     uint32_t b0, uint32_t b1) {
    asm("mma.sync.aligned.m16n8k16.row.col.f32.bf16.bf16.f32 "
        "{%0,%1,%2,%3}, {%4,%5,%6,%7}, {%8,%9}, {%0,%1,%2,%3};"
        : "+f"(c[0]), "+f"(c[1]), "+f"(c[2]), "+f"(c[3])
        : "r"(a0), "r"(a1), "r"(a2), "r"(a3), "r"(b0), "r"(b1));
}

// pack two f32 -> bf16x2 {low=a, high=b} (rn)
__device__ __forceinline__ uint32_t pack_bf16x2(float a, float b) {
    uint32_t r;
    asm("cvt.rn.bf16x2.f32 %0, %1, %2;" : "=r"(r) : "f"(b), "f"(a));
    return r;
}

// ---------------------------------------------------------------------------
// Weight prep: split 6 weights into bf16 hi(trunc)/lo swizzled tiles
// ---------------------------------------------------------------------------
__global__ void prep_w(const float* __restrict__ W0, const float* __restrict__ W1,
                       const float* __restrict__ W2, const float* __restrict__ W3,
                       const float* __restrict__ W4, const float* __restrict__ W5)
{
    const float* W;
    switch (blockIdx.x) {
        case 0: W = W0; break; case 1: W = W1; break; case 2: W = W2; break;
        case 3: W = W3; break; case 4: W = W4; break; default: W = W5; break;
    }
    unsigned char* out = g_wbf + (size_t)blockIdx.x * 65536;
    for (int idx = threadIdx.x; idx < 16384; idx += blockDim.x) {
        int row = idx >> 7, col = idx & 127;
        float x = W[idx];
        uint32_t xu = __float_as_uint(x);
        uint32_t hi = xu & 0xffff0000u;                  // truncated bf16
        float lo = x - __uint_as_float(hi);
        __nv_bfloat16 lb = __float2bfloat16(lo);
        int off = sw_off(row, col);
        *reinterpret_cast<uint16_t*>(out + off) = (uint16_t)(hi >> 16);
        *reinterpret_cast<__nv_bfloat16*>(out + 32768 + off) = lb;
    }
}

// ---------------------------------------------------------------------------
// Shared pieces: W copy, X convert, MMA core.
// Block = 512 threads (16 warps, grid 4(M)x4(N over 256 combined cols)).
// Warp tile: M=32 (2 m16 frags), N=64 (8 n8 frags). acc[2][8][4].
// ---------------------------------------------------------------------------
__device__ __forceinline__ void copy_weights(char* sm, int w1idx, int w2idx) {
    const uint4* s1h = reinterpret_cast<const uint4*>(g_wbf + (size_t)w1idx * 65536);
    const uint4* s2h = reinterpret_cast<const uint4*>(g_wbf + (size_t)w2idx * 65536);
    uint4* d1 = reinterpret_cast<uint4*>(sm + SW1HI);   // hi+lo contiguous 64KB
    uint4* d2 = reinterpret_cast<uint4*>(sm + SW2HI);
    int tid = threadIdx.x;
    #pragma unroll
    for (int i = 0; i < 8; i++) {
        int j = tid + i * 512;   // 0..4095 uint4 = 64KB
        d1[j] = __ldg(&s1h[j]);
        d2[j] = __ldg(&s2h[j]);
    }
}

__device__ __forceinline__ void convert_x(char* sm, const float* __restrict__ X,
                                          int m0, int M) {
    int tid = threadIdx.x;
    int r = tid >> 2;              // 0..127
    int ch = (tid & 3) * 32;       // 32-col strip per thread
    bool valid = (m0 + r) < M;
    const float* xp = X + (size_t)(m0 + r) * 128 + ch;
    #pragma unroll
    for (int u = 0; u < 8; u++) {
        int c = ch + u * 4;
        float4 xv = make_float4(0.f, 0.f, 0.f, 0.f);
        if (valid) xv = *reinterpret_cast<const float4*>(xp + u * 4);
        uint32_t u0 = __float_as_uint(xv.x), u1 = __float_as_uint(xv.y);
        uint32_t u2 = __float_as_uint(xv.z), u3 = __float_as_uint(xv.w);
        uint32_t h01 = __byte_perm(u0, u1, 0x7632);
        uint32_t h23 = __byte_perm(u2, u3, 0x7632);
        float l0 = xv.x - __uint_as_float(u0 & 0xffff0000u);
        float l1 = xv.y - __uint_as_float(u1 & 0xffff0000u);
        float l2 = xv.z - __uint_as_float(u2 & 0xffff0000u);
        float l3 = xv.w - __uint_as_float(u3 & 0xffff0000u);
        int off = sw_off(r, c);
        *reinterpret_cast<uint2*>(sm + SXHI + off) = make_uint2(h01, h23);
        *reinterpret_cast<uint2*>(sm + SXLO + off) =
            make_uint2(pack_bf16x2(l0, l1), pack_bf16x2(l2, l3));
    }
}

__device__ __forceinline__ void mma_tile(const char* sm, float acc[2][8][4]) {
    const int lane = threadIdx.x & 31;
    const int wid  = threadIdx.x >> 5;   // 0..15
    const int wm = wid & 3;        // M slice: wm*32
    const int wn = wid >> 2;       // combined N slice: wn*64 (0..3)
    const int g  = lane >> 2;
    const int t4 = (lane & 3) * 4;

    const char* xhi = sm + SXHI;
    const char* xlo = sm + SXLO;
    const char* wh = sm + ((wn >= 2) ? SW2HI : SW1HI);
    const char* wl = wh + 32768;

    const int arow = (wm * 32 + g) * 256 + t4;
    const int brow = ((wn & 1) * 64 + g) * 256 + t4;

    #pragma unroll
    for (int i = 0; i < 2; i++)
        #pragma unroll
        for (int j = 0; j < 8; j++)
            #pragma unroll
            for (int r = 0; r < 4; r++) acc[i][j][r] = 0.f;

    #pragma unroll
    for (int ks = 0; ks < 8; ks++) {
        const int cx0 = (((2 * ks) ^ g) << 4);
        const int cx1 = (((2 * ks + 1) ^ g) << 4);

        uint32_t ah[2][4], al[2][4];
        #pragma unroll
        for (int i = 0; i < 2; i++) {
            int r0 = arow + i * 16 * 256;
            int r8 = r0 + 8 * 256;
            ah[i][0] = *reinterpret_cast<const uint32_t*>(xhi + r0 + cx0);
            ah[i][1] = *reinterpret_cast<const uint32_t*>(xhi + r8 + cx0);
            ah[i][2] = *reinterpret_cast<const uint32_t*>(xhi + r0 + cx1);
            ah[i][3] = *reinterpret_cast<const uint32_t*>(xhi + r8 + cx1);
            al[i][0] = *reinterpret_cast<const uint32_t*>(xlo + r0 + cx0);
            al[i][1] = *reinterpret_cast<const uint32_t*>(xlo + r8 + cx0);
            al[i][2] = *reinterpret_cast<const uint32_t*>(xlo + r0 + cx1);
            al[i][3] = *reinterpret_cast<const uint32_t*>(xlo + r8 + cx1);
        }
        #pragma unroll
        for (int j = 0; j < 8; j++) {
            int rb = brow + j * 8 * 256;
            uint32_t bh0 = *reinterpret_cast<const uint32_t*>(wh + rb + cx0);
            uint32_t bh1 = *reinterpret_cast<const uint32_t*>(wh + rb + cx1);
            uint32_t bl0 = *reinterpret_cast<const uint32_t*>(wl + rb + cx0);
            uint32_t bl1 = *reinterpret_cast<const uint32_t*>(wl + rb + cx1);
            #pragma unroll
            for (int i = 0; i < 2; i++) {
                hmma(acc[i][j], ah[i][0], ah[i][1], ah[i][2], ah[i][3], bh0, bh1);
                hmma(acc[i][j], al[i][0], al[i][1], al[i][2], al[i][3], bh0, bh1);
                hmma(acc[i][j], ah[i][0], ah[i][1], ah[i][2], ah[i][3], bl0, bl1);
            }
        }
    }
}

// ---------------------------------------------------------------------------
// Node GEMM: Y1 = X@W1^T + b1, Y2 = X@W2^T + b2 (128-row tile)
// ---------------------------------------------------------------------------
__global__ __launch_bounds__(512, 1) void gemm_mma2(
    const float* __restrict__ X, int w1idx, int w2idx,
    const float* __restrict__ b1, const float* __restrict__ b2,
    float* __restrict__ Y1, float* __restrict__ Y2, int M)
{
    extern __shared__ char sm[];
    const int m0 = blockIdx.x * 128;
    copy_weights(sm, w1idx, w2idx);
    convert_x(sm, X, m0, M);
    __syncthreads();

    float acc[2][8][4];
    mma_tile(sm, acc);

    const int lane = threadIdx.x & 31;
    const int wid  = threadIdx.x >> 5;
    const int wm = wid & 3, wn = wid >> 2;
    const int g = lane >> 2, t2 = (lane & 3) * 2;

    const float* bias = (wn >= 2) ? b2 : b1;
    float* Y = (wn >= 2) ? Y2 : Y1;
    float2 bb[8];
    #pragma unroll
    for (int j = 0; j < 8; j++) {
        int colw = (wn & 1) * 64 + j * 8 + t2;
        bb[j] = *reinterpret_cast<const float2*>(&bias[colw]);
    }
    #pragma unroll
    for (int i = 0; i < 2; i++) {
        int rlo = m0 + wm * 32 + i * 16 + g;
        int rhi = rlo + 8;
        #pragma unroll
        for (int j = 0; j < 8; j++) {
            int colw = (wn & 1) * 64 + j * 8 + t2;
            if (rlo < M) {
                float2 o = make_float2(acc[i][j][0] + bb[j].x, acc[i][j][1] + bb[j].y);
                *reinterpret_cast<float2*>(&Y[(size_t)rlo * 128 + colw]) = o;
            }
            if (rhi < M) {
                float2 o = make_float2(acc[i][j][2] + bb[j].x, acc[i][j][3] + bb[j].y);
                *reinterpret_cast<float2*>(&Y[(size_t)rhi * 128 + colw]) = o;
            }
        }
    }
}

// ---------------------------------------------------------------------------
// Fused edge kernel: block = 128 edges, 512 threads.
//   mma (both We and Wev) -> eproj to smem P, eres stays in regs
//   edge math (dot / head-softmax / red.v4 agg / LN / silu) -> P
//   y = eres + bev + P
// ---------------------------------------------------------------------------
__global__ __launch_bounds__(512, 1) void edge_fused(
    const float* __restrict__ edge_feats,
    const float* __restrict__ be, const float* __restrict__ bev,
    const int* __restrict__ src, const int* __restrict__ dst,
    const float* __restrict__ q, const float* __restrict__ k,
    const float* __restrict__ v,
    const float* __restrict__ ln_eg, const float* __restrict__ ln_eb,
    float* __restrict__ agg, float* __restrict__ y_out)
{
    extern __shared__ char sm[];
    float* P = reinterpret_cast<float*>(sm + SP_OFF);   // [128][132]
    const int e0 = blockIdx.x * 128;

    copy_weights(sm, 4, 5);            // We, Wev
    convert_x(sm, edge_feats, e0, EE);
    __syncthreads();

    float acc[2][8][4];
    mma_tile(sm, acc);
    __syncthreads();   // X region dead; P can be written

    const int lane = threadIdx.x & 31;
    const int wid  = threadIdx.x >> 5;   // 0..15
    const int wm = wid & 3, wn = wid >> 2;
    const int g = lane >> 2, t2 = (lane & 3) * 2;

    const float* bias = (wn >= 2) ? bev : be;
    float2 bb[8];
    #pragma unroll
    for (int j = 0; j < 8; j++) {
        int colw = (wn & 1) * 64 + j * 8 + t2;
        bb[j] = *reinterpret_cast<const float2*>(&bias[colw]);
    }

    // Phase A: eproj + be -> P (warps wn<2 hold the We product)
    if (wn < 2) {
        #pragma unroll
        for (int i = 0; i < 2; i++) {
            int rlo = wm * 32 + i * 16 + g;
            int rhi = rlo + 8;
            #pragma unroll
            for (int j = 0; j < 8; j++) {
                int colw = (wn & 1) * 64 + j * 8 + t2;
                P[rlo * 132 + colw]     = acc[i][j][0] + bb[j].x;
                P[rlo * 132 + colw + 1] = acc[i][j][1] + bb[j].y;
                P[rhi * 132 + colw]     = acc[i][j][2] + bb[j].x;
                P[rhi * 132 + colw + 1] = acc[i][j][3] + bb[j].y;
            }
        }
    }
    __syncthreads();

    // Phase B: edge math; 16 warps x 8 rows = 128 edges.
    // Lane owns 4 consecutive cols (head = lane>>3).
    {
        const unsigned FULL = 0xffffffffu;
        float4 ge = *reinterpret_cast<const float4*>(&ln_eg[4 * lane]);
        float4 gb = *reinterpret_cast<const float4*>(&ln_eb[4 * lane]);

        #pragma unroll 1
        for (int it = 0; it < 8; it++) {
            int row = wid * 8 + it;
            int e = e0 + row;
            int s = __ldg(&src[e]);
            int d = __ldg(&dst[e]);
            float4 q4 = __ldg(reinterpret_cast<const float4*>(&q[(size_t)s * 128 + 4 * lane]));
            float4 k4 = __ldg(reinterpret_cast<const float4*>(&k[(size_t)d * 128 + 4 * lane]));
            float4 v4 = __ldg(reinterpret_cast<const float4*>(&v[(size_t)s * 128 + 4 * lane]));

            float pd = q4.x * k4.x + q4.y * k4.y + q4.z * k4.z + q4.w * k4.w;
            pd += __shfl_xor_sync(FULL, pd, 1);
            pd += __shfl_xor_sync(FULL, pd, 2);
            pd += __shfl_xor_sync(FULL, pd, 4);

            float4 m4 = *reinterpret_cast<const float4*>(&P[row * 132 + 4 * lane]);
            m4.x = fmaf(pd, INV_SCALE, m4.x);
            m4.y = fmaf(pd, INV_SCALE, m4.y);
            m4.z = fmaf(pd, INV_SCALE, m4.z);
            m4.w = fmaf(pd, INV_SCALE, m4.w);

            // softmax over the 4 heads: partners at lane^8, lane^16, lane^24
            float4 mx = m4;
            #pragma unroll
            for (int off = 8; off <= 16; off <<= 1) {
                mx.x = fmaxf(mx.x, __shfl_xor_sync(FULL, mx.x, off));
                mx.y = fmaxf(mx.y, __shfl_xor_sync(FULL, mx.y, off));
                mx.z = fmaxf(mx.z, __shfl_xor_sync(FULL, mx.z, off));
                mx.w = fmaxf(mx.w, __shfl_xor_sync(FULL, mx.w, off));
            }
            float4 ex;
            ex.x = __expf(m4.x - mx.x); ex.y = __expf(m4.y - mx.y);
            ex.z = __expf(m4.z - mx.z); ex.w = __expf(m4.w - mx.w);
            float4 sx = ex;
            #pragma unroll
            for (int off = 8; off <= 16; off <<= 1) {
                sx.x += __shfl_xor_sync(FULL, sx.x, off);
                sx.y += __shfl_xor_sync(FULL, sx.y, off);
                sx.z += __shfl_xor_sync(FULL, sx.z, off);
                sx.w += __shfl_xor_sync(FULL, sx.w, off);
            }
            float4 msg;
            msg.x = v4.x * ex.x / sx.x;
            msg.y = v4.y * ex.y / sx.y;
            msg.z = v4.z * ex.z / sx.z;
            msg.w = v4.w * ex.w / sx.w;
            float* ap = &agg[(size_t)d * 128 + 4 * lane];
            asm volatile("red.global.add.v4.f32 [%0], {%1, %2, %3, %4};"
                         :: "l"(ap), "f"(msg.x), "f"(msg.y), "f"(msg.z), "f"(msg.w)
                         : "memory");

            // layernorm over 128 cols
            float ls = m4.x + m4.y + m4.z + m4.w;
            float lq = m4.x * m4.x + m4.y * m4.y + m4.z * m4.z + m4.w * m4.w;
            #pragma unroll
            for (int off = 16; off > 0; off >>= 1) {
                ls += __shfl_xor_sync(FULL, ls, off);
                lq += __shfl_xor_sync(FULL, lq, off);
            }
            float mu = ls * (1.0f / 128.0f);
            float var = lq * (1.0f / 128.0f) - mu * mu;
            float rs = rsqrtf(var + LN_EPS);

            float4 sil;
            {
                float t0 = fmaf((m4.x - mu) * rs, ge.x, gb.x);
                float t1 = fmaf((m4.y - mu) * rs, ge.y, gb.y);
                float t2f = fmaf((m4.z - mu) * rs, ge.z, gb.z);
                float t3 = fmaf((m4.w - mu) * rs, ge.w, gb.w);
                sil.x = t0 / (1.0f + __expf(-t0));
                sil.y = t1 / (1.0f + __expf(-t1));
                sil.z = t2f / (1.0f + __expf(-t2f));
                sil.w = t3 / (1.0f + __expf(-t3));
            }
            *reinterpret_cast<float4*>(&P[row * 132 + 4 * lane]) = sil;
        }
    }
    __syncthreads();

    // Phase C: y = eres + bev + silu   (warps wn>=2 hold the Wev product)
    if (wn >= 2) {
        #pragma unroll
        for (int i = 0; i < 2; i++) {
            int rlo = wm * 32 + i * 16 + g;
            int rhi = rlo + 8;
            #pragma unroll
            for (int j = 0; j < 8; j++) {
                int colw = (wn & 1) * 64 + j * 8 + t2;
                float2 o0, o1;
                o0.x = acc[i][j][0] + bb[j].x + P[rlo * 132 + colw];
                o0.y = acc[i][j][1] + bb[j].y + P[rlo * 132 + colw + 1];
                o1.x = acc[i][j][2] + bb[j].x + P[rhi * 132 + colw];
                o1.y = acc[i][j][3] + bb[j].y + P[rhi * 132 + colw + 1];
                *reinterpret_cast<float2*>(&y_out[(size_t)(e0 + rlo) * 128 + colw]) = o0;
                *reinterpret_cast<float2*>(&y_out[(size_t)(e0 + rhi) * 128 + colw]) = o1;
            }
        }
    }
}

// ---------------------------------------------------------------------------
// Zero agg buffer
// ---------------------------------------------------------------------------
__global__ void zero_kernel(float* __restrict__ p, int n4)
{
    int i = blockIdx.x * blockDim.x + threadIdx.x;
    if (i < n4) reinterpret_cast<float4*>(p)[i] = make_float4(0.f, 0.f, 0.f, 0.f);
}

// ---------------------------------------------------------------------------
// Node finalize: x = node_res + silu(LN_128(agg))
// ---------------------------------------------------------------------------
__global__ __launch_bounds__(256) void node_kernel(
    const float* __restrict__ agg, const float* __restrict__ nres,
    const float* __restrict__ ln_ng, const float* __restrict__ ln_nb,
    float* __restrict__ x_out)
{
    int warp = (blockIdx.x * blockDim.x + threadIdx.x) >> 5;
    int lane = threadIdx.x & 31;
    if (warp >= NN) return;

    size_t base = (size_t)warp * 128 + lane;
    float a[4];
    #pragma unroll
    for (int h = 0; h < 4; h++) a[h] = agg[base + h * 32];

    float ssum = a[0] + a[1] + a[2] + a[3];
    float ssq  = a[0]*a[0] + a[1]*a[1] + a[2]*a[2] + a[3]*a[3];
    #pragma unroll
    for (int off = 16; off > 0; off >>= 1) {
        ssum += __shfl_xor_sync(0xffffffffu, ssum, off);
        ssq  += __shfl_xor_sync(0xffffffffu, ssq,  off);
    }
    float mu  = ssum * (1.0f / 128.0f);
    float var = ssq * (1.0f / 128.0f) - mu * mu;
    float rs  = rsqrtf(var + LN_EPS);

    #pragma unroll
    for (int h = 0; h < 4; h++) {
        float g = ln_ng[h * 32 + lane];
        float bb = ln_nb[h * 32 + lane];
        float t = fmaf((a[h] - mu) * rs, g, bb);
        float sil = t / (1.0f + __expf(-t));
        x_out[base + h * 32] = sil + nres[base + h * 32];
    }
}

// ---------------------------------------------------------------------------
// Launch
// ---------------------------------------------------------------------------
extern "C" void kernel_launch(void* const* d_in, const int* in_sizes, int n_in,
                              void* d_out, int out_size)
{
    const float* node_feats = (const float*)d_in[0];
    const float* edge_feats = (const float*)d_in[1];
    const int*   src        = (const int*)d_in[2];
    const int*   dst        = (const int*)d_in[3];
    const float* Wq   = (const float*)d_in[4];
    const float* bq   = (const float*)d_in[5];
    const float* Wk   = (const float*)d_in[6];
    const float* bk   = (const float*)d_in[7];
    const float* Wv   = (const float*)d_in[8];
    const float* bv   = (const float*)d_in[9];
    const float* We   = (const float*)d_in[10];
    const float* be   = (const float*)d_in[11];
    const float* Wev  = (const float*)d_in[12];
    const float* bev  = (const float*)d_in[13];
    const float* Wout = (const float*)d_in[14];
    const float* bout = (const float*)d_in[15];
    const float* ln_ng = (const float*)d_in[16];
    const float* ln_nb = (const float*)d_in[17];
    const float* ln_eg = (const float*)d_in[18];
    const float* ln_eb = (const float*)d_in[19];

    float* scratch = nullptr;
    cudaGetSymbolAddress((void**)&scratch, g_scratch);
    float* q    = scratch;
    float* kk   = q    + (size_t)NN * 128;
    float* vv   = kk   + (size_t)NN * 128;
    float* nres = vv   + (size_t)NN * 128;
    float* agg  = nres + (size_t)NN * 128;

    float* x_out = (float*)d_out;
    float* y_out = x_out + (size_t)NN * 128;

    static bool attr_set = false;
    if (!attr_set) {
        cudaFuncSetAttribute(gemm_mma2, cudaFuncAttributeMaxDynamicSharedMemorySize, SMEM_GEMM);
        cudaFuncSetAttribute(edge_fused, cudaFuncAttributeMaxDynamicSharedMemorySize, SMEM_EDGE);
        attr_set = true;
    }

    // g_wbf order: 0=Wq 1=Wk 2=Wv 3=Wout 4=We 5=Wev
    prep_w<<<6, 256>>>(Wq, Wk, Wv, Wout, We, Wev);

    const int node_blocks = (NN + 127) / 128;   // 391
    const int edge_blocks = EE / 128;           // 3125

    gemm_mma2<<<node_blocks, 512, SMEM_GEMM>>>(node_feats, 0, 1, bq, bk, q, kk, NN);
    gemm_mma2<<<node_blocks, 512, SMEM_GEMM>>>(node_feats, 2, 3, bv, bout, vv, nres, NN);

    int n4 = NN * 128 / 4;
    zero_kernel<<<(n4 + 255) / 256, 256>>>(agg, n4);

    edge_fused<<<edge_blocks, 512, SMEM_EDGE>>>(
        edge_feats, be, bev, src, dst, q, kk, vv, ln_eg, ln_eb, agg, y_out);

    node_kernel<<<NN / 8, 256>>>(agg, nres, ln_ng, ln_nb, x_out);
}

// round 6
// speedup vs baseline: 3.0464x; 1.0722x over previous
#include <cuda_runtime.h>
#include <cuda_bf16.h>
#include <math.h>
#include <stdint.h>

#define NN 50000
#define EE 400000
#define NBLK 391            // ceil(NN/128)
#define ZBLK 391            // zero-agg blocks appended to node gemm launch
#define INV_SCALE 0.17677669529663687f   // 1/sqrt(32)
#define LN_EPS 1e-5f

// Scratch: q, k, v, nres, agg (5*N*128 = 32M floats)
__device__ float g_scratch[32000000];
// bf16 hi/lo swizzled weight tiles: 6 weights x (32KB hi + 32KB lo)
__device__ __align__(256) unsigned char g_wbf[6 * 65536];

// ---- smem byte offsets ----
#define SW1HI 0
#define SW1LO 32768
#define SW2HI 65536
#define SW2LO 98304
#define SXHI  131072
#define SXLO  163840
#define SMEM_GEMM 196608
// P (float[128][132]) aliases the X region in the edge kernel
#define SP_OFF 131072
#define SMEM_EDGE (131072 + 128 * 132 * 4)   // 198656

// Swizzled byte offset in a 128x128 bf16 K-major tile (256B rows, 16B chunks,
// chunk ^= row&7 -> conflict-free for both row-parallel and k-parallel access).
__device__ __host__ __forceinline__ int sw_off(int row, int col) {
    return row * 256 + ((((col >> 3) ^ (row & 7)) & 15) << 4) + (col & 7) * 2;
}

__device__ __forceinline__ uint32_t smem_u32(const void* p) {
    uint32_t a;
    asm("{ .reg .u64 t; cvta.to.shared.u64 t, %1; cvt.u32.u64 %0, t; }"
        : "=r"(a) : "l"(p));
    return a;
}

__device__ __forceinline__ void hmma(float* c, uint32_t a0, uint32_t a1,
                                     uint32_t a2, uint32_t a3,
                                     uint32_t b0, uint32_t b1) {
    asm("mma.sync.aligned.m16n8k16.row.col.f32.bf16.bf16.f32 "
        "{%0,%1,%2,%3}, {%4,%5,%6,%7}, {%8,%9}, {%0,%1,%2,%3};"
        : "+f"(c[0]), "+f"(c[1]), "+f"(c[2]), "+f"(c[3])
        : "r"(a0), "r"(a1), "r"(a2), "r"(a3), "r"(b0), "r"(b1));
}

// pack two f32 -> bf16x2 {low=a, high=b} (rn)
__device__ __forceinline__ uint32_t pack_bf16x2(float a, float b) {
    uint32_t r;
    asm("cvt.rn.bf16x2.f32 %0, %1, %2;" : "=r"(r) : "f"(b), "f"(a));
    return r;
}

// ---------------------------------------------------------------------------
// Weight prep: split 6 weights into bf16 hi(trunc)/lo swizzled tiles
// ---------------------------------------------------------------------------
__global__ void prep_w(const float* __restrict__ W0, const float* __restrict__ W1,
                       const float* __restrict__ W2, const float* __restrict__ W3,
                       const float* __restrict__ W4, const float* __restrict__ W5)
{
    const float* W;
    switch (blockIdx.x) {
        case 0: W = W0; break; case 1: W = W1; break; case 2: W = W2; break;
        case 3: W = W3; break; case 4: W = W4; break; default: W = W5; break;
    }
    unsigned char* out = g_wbf + (size_t)blockIdx.x * 65536;
    for (int idx = threadIdx.x; idx < 16384; idx += blockDim.x) {
        int row = idx >> 7, col = idx & 127;
        float x = W[idx];
        uint32_t xu = __float_as_uint(x);
        uint32_t hi = xu & 0xffff0000u;                  // truncated bf16
        float lo = x - __uint_as_float(hi);
        __nv_bfloat16 lb = __float2bfloat16(lo);
        int off = sw_off(row, col);
        *reinterpret_cast<uint16_t*>(out + off) = (uint16_t)(hi >> 16);
        *reinterpret_cast<__nv_bfloat16*>(out + 32768 + off) = lb;
    }
}

// ---------------------------------------------------------------------------
// Shared pieces. Block = 512 threads (16 warps, grid 4(M)x4(N combined)).
// Warp tile: M=32 (2 m16 frags), N=64 (8 n8 frags). acc[2][8][4].
// ---------------------------------------------------------------------------
__device__ __forceinline__ void copy_weights_async(char* sm, int w1idx, int w2idx) {
    uint32_t d1 = smem_u32(sm + SW1HI);
    uint32_t d2 = smem_u32(sm + SW2HI);
    const char* s1 = reinterpret_cast<const char*>(g_wbf + (size_t)w1idx * 65536);
    const char* s2 = reinterpret_cast<const char*>(g_wbf + (size_t)w2idx * 65536);
    int tid = threadIdx.x;
    #pragma unroll
    for (int i = 0; i < 8; i++) {
        int j = (tid + i * 512) * 16;   // 64KB per weight (hi+lo contiguous)
        asm volatile("cp.async.cg.shared.global [%0], [%1], 16;"
                     :: "r"(d1 + j), "l"(s1 + j));
        asm volatile("cp.async.cg.shared.global [%0], [%1], 16;"
                     :: "r"(d2 + j), "l"(s2 + j));
    }
    asm volatile("cp.async.commit_group;");
}

__device__ __forceinline__ void convert_x(char* sm, const float* __restrict__ X,
                                          int m0, int M) {
    int tid = threadIdx.x;
    int r = tid >> 2;              // 0..127
    int ch = (tid & 3) * 32;       // 32-col strip per thread
    bool valid = (m0 + r) < M;
    const float* xp = X + (size_t)(m0 + r) * 128 + ch;
    #pragma unroll
    for (int u = 0; u < 8; u++) {
        int c = ch + u * 4;
        float4 xv = make_float4(0.f, 0.f, 0.f, 0.f);
        if (valid) xv = *reinterpret_cast<const float4*>(xp + u * 4);
        uint32_t u0 = __float_as_uint(xv.x), u1 = __float_as_uint(xv.y);
        uint32_t u2 = __float_as_uint(xv.z), u3 = __float_as_uint(xv.w);
        uint32_t h01 = __byte_perm(u0, u1, 0x7632);
        uint32_t h23 = __byte_perm(u2, u3, 0x7632);
        float l0 = xv.x - __uint_as_float(u0 & 0xffff0000u);
        float l1 = xv.y - __uint_as_float(u1 & 0xffff0000u);
        float l2 = xv.z - __uint_as_float(u2 & 0xffff0000u);
        float l3 = xv.w - __uint_as_float(u3 & 0xffff0000u);
        int off = sw_off(r, c);
        *reinterpret_cast<uint2*>(sm + SXHI + off) = make_uint2(h01, h23);
        *reinterpret_cast<uint2*>(sm + SXLO + off) =
            make_uint2(pack_bf16x2(l0, l1), pack_bf16x2(l2, l3));
    }
}

__device__ __forceinline__ void mma_tile(const char* sm, float acc[2][8][4]) {
    const int lane = threadIdx.x & 31;
    const int wid  = threadIdx.x >> 5;   // 0..15
    const int wm = wid & 3;        // M slice: wm*32
    const int wn = wid >> 2;       // combined N slice: wn*64 (0..3)
    const int g  = lane >> 2;
    const int t4 = (lane & 3) * 4;

    const char* xhi = sm + SXHI;
    const char* xlo = sm + SXLO;
    const char* wh = sm + ((wn >= 2) ? SW2HI : SW1HI);
    const char* wl = wh + 32768;

    const int arow = (wm * 32 + g) * 256 + t4;
    const int brow = ((wn & 1) * 64 + g) * 256 + t4;

    #pragma unroll
    for (int i = 0; i < 2; i++)
        #pragma unroll
        for (int j = 0; j < 8; j++)
            #pragma unroll
            for (int r = 0; r < 4; r++) acc[i][j][r] = 0.f;

    #pragma unroll
    for (int ks = 0; ks < 8; ks++) {
        const int cx0 = (((2 * ks) ^ g) << 4);
        const int cx1 = (((2 * ks + 1) ^ g) << 4);

        uint32_t ah[2][4], al[2][4];
        #pragma unroll
        for (int i = 0; i < 2; i++) {
            int r0 = arow + i * 16 * 256;
            int r8 = r0 + 8 * 256;
            ah[i][0] = *reinterpret_cast<const uint32_t*>(xhi + r0 + cx0);
            ah[i][1] = *reinterpret_cast<const uint32_t*>(xhi + r8 + cx0);
            ah[i][2] = *reinterpret_cast<const uint32_t*>(xhi + r0 + cx1);
            ah[i][3] = *reinterpret_cast<const uint32_t*>(xhi + r8 + cx1);
            al[i][0] = *reinterpret_cast<const uint32_t*>(xlo + r0 + cx0);
            al[i][1] = *reinterpret_cast<const uint32_t*>(xlo + r8 + cx0);
            al[i][2] = *reinterpret_cast<const uint32_t*>(xlo + r0 + cx1);
            al[i][3] = *reinterpret_cast<const uint32_t*>(xlo + r8 + cx1);
        }
        #pragma unroll
        for (int j = 0; j < 8; j++) {
            int rb = brow + j * 8 * 256;
            uint32_t bh0 = *reinterpret_cast<const uint32_t*>(wh + rb + cx0);
            uint32_t bh1 = *reinterpret_cast<const uint32_t*>(wh + rb + cx1);
            uint32_t bl0 = *reinterpret_cast<const uint32_t*>(wl + rb + cx0);
            uint32_t bl1 = *reinterpret_cast<const uint32_t*>(wl + rb + cx1);
            #pragma unroll
            for (int i = 0; i < 2; i++) {
                hmma(acc[i][j], ah[i][0], ah[i][1], ah[i][2], ah[i][3], bh0, bh1);
                hmma(acc[i][j], al[i][0], al[i][1], al[i][2], al[i][3], bh0, bh1);
                hmma(acc[i][j], ah[i][0], ah[i][1], ah[i][2], ah[i][3], bl0, bl1);
            }
        }
    }
}

// ---------------------------------------------------------------------------
// Node GEMMs merged: half 0 -> (Wq,Wk)->(q,k), half 1 -> (Wv,Wout)->(v,nres).
// Trailing ZBLK blocks zero the agg buffer.
// ---------------------------------------------------------------------------
__global__ __launch_bounds__(512, 1) void gemm_node(
    const float* __restrict__ X,
    const float* __restrict__ bq, const float* __restrict__ bk,
    const float* __restrict__ bv, const float* __restrict__ bout,
    float* __restrict__ q, float* __restrict__ kk,
    float* __restrict__ vv, float* __restrict__ nres,
    float* __restrict__ agg)
{
    if (blockIdx.x >= 2 * NBLK) {
        // zero agg: NN*128/4 = 1,600,000 float4
        int idx = (blockIdx.x - 2 * NBLK) * 512 + threadIdx.x;
        const int stride = ZBLK * 512;
        float4 z = make_float4(0.f, 0.f, 0.f, 0.f);
        for (int i = idx; i < NN * 32; i += stride)
            reinterpret_cast<float4*>(agg)[i] = z;
        return;
    }

    extern __shared__ char sm[];
    const int half = blockIdx.x / NBLK;
    const int m0 = (blockIdx.x % NBLK) * 128;
    const int w1idx = half * 2, w2idx = half * 2 + 1;
    const float* b1 = half ? bv : bq;
    const float* b2 = half ? bout : bk;
    float* Y1 = half ? vv : q;
    float* Y2 = half ? nres : kk;

    copy_weights_async(sm, w1idx, w2idx);
    convert_x(sm, X, m0, NN);
    asm volatile("cp.async.wait_group 0;");
    __syncthreads();

    float acc[2][8][4];
    mma_tile(sm, acc);

    const int lane = threadIdx.x & 31;
    const int wid  = threadIdx.x >> 5;
    const int wm = wid & 3, wn = wid >> 2;
    const int g = lane >> 2, t2 = (lane & 3) * 2;

    const float* bias = (wn >= 2) ? b2 : b1;
    float* Y = (wn >= 2) ? Y2 : Y1;
    float2 bb[8];
    #pragma unroll
    for (int j = 0; j < 8; j++) {
        int colw = (wn & 1) * 64 + j * 8 + t2;
        bb[j] = *reinterpret_cast<const float2*>(&bias[colw]);
    }
    #pragma unroll
    for (int i = 0; i < 2; i++) {
        int rlo = m0 + wm * 32 + i * 16 + g;
        int rhi = rlo + 8;
        #pragma unroll
        for (int j = 0; j < 8; j++) {
            int colw = (wn & 1) * 64 + j * 8 + t2;
            if (rlo < NN) {
                float2 o = make_float2(acc[i][j][0] + bb[j].x, acc[i][j][1] + bb[j].y);
                *reinterpret_cast<float2*>(&Y[(size_t)rlo * 128 + colw]) = o;
            }
            if (rhi < NN) {
                float2 o = make_float2(acc[i][j][2] + bb[j].x, acc[i][j][3] + bb[j].y);
                *reinterpret_cast<float2*>(&Y[(size_t)rhi * 128 + colw]) = o;
            }
        }
    }
}

// ---------------------------------------------------------------------------
// Fused edge kernel: block = 128 edges, 512 threads.
// ---------------------------------------------------------------------------
__global__ __launch_bounds__(512, 1) void edge_fused(
    const float* __restrict__ edge_feats,
    const float* __restrict__ be, const float* __restrict__ bev,
    const int* __restrict__ src, const int* __restrict__ dst,
    const float* __restrict__ q, const float* __restrict__ k,
    const float* __restrict__ v,
    const float* __restrict__ ln_eg, const float* __restrict__ ln_eb,
    float* __restrict__ agg, float* __restrict__ y_out)
{
    extern __shared__ char sm[];
    float* P = reinterpret_cast<float*>(sm + SP_OFF);   // [128][132]
    const int e0 = blockIdx.x * 128;

    copy_weights_async(sm, 4, 5);      // We, Wev
    convert_x(sm, edge_feats, e0, EE);
    asm volatile("cp.async.wait_group 0;");
    __syncthreads();

    float acc[2][8][4];
    mma_tile(sm, acc);
    __syncthreads();   // X region dead; P can be written

    const int lane = threadIdx.x & 31;
    const int wid  = threadIdx.x >> 5;   // 0..15
    const int wm = wid & 3, wn = wid >> 2;
    const int g = lane >> 2, t2 = (lane & 3) * 2;

    const float* bias = (wn >= 2) ? bev : be;
    float2 bb[8];
    #pragma unroll
    for (int j = 0; j < 8; j++) {
        int colw = (wn & 1) * 64 + j * 8 + t2;
        bb[j] = *reinterpret_cast<const float2*>(&bias[colw]);
    }

    // Preload this warp's 8 edges' src (lanes 0-7) / dst (lanes 8-15) indices.
    int sd = 0;
    {
        int eidx = e0 + wid * 8 + (lane & 7);
        if (lane < 16) sd = __ldg((lane < 8) ? &src[eidx] : &dst[eidx]);
    }

    // Phase A: eproj + be -> P (warps wn<2 hold the We product)
    if (wn < 2) {
        #pragma unroll
        for (int i = 0; i < 2; i++) {
            int rlo = wm * 32 + i * 16 + g;
            int rhi = rlo + 8;
            #pragma unroll
            for (int j = 0; j < 8; j++) {
                int colw = (wn & 1) * 64 + j * 8 + t2;
                P[rlo * 132 + colw]     = acc[i][j][0] + bb[j].x;
                P[rlo * 132 + colw + 1] = acc[i][j][1] + bb[j].y;
                P[rhi * 132 + colw]     = acc[i][j][2] + bb[j].x;
                P[rhi * 132 + colw + 1] = acc[i][j][3] + bb[j].y;
            }
        }
    }
    __syncthreads();

    // Phase B: edge math; 16 warps x 8 rows = 128 edges.
    // Lane owns 4 consecutive cols (head = lane>>3). q/k gathers prefetched
    // one iteration ahead; indices come from the sd register via shfl.
    {
        const unsigned FULL = 0xffffffffu;
        float4 ge = *reinterpret_cast<const float4*>(&ln_eg[4 * lane]);
        float4 gb = *reinterpret_cast<const float4*>(&ln_eb[4 * lane]);

        int s = __shfl_sync(FULL, sd, 0);
        int d = __shfl_sync(FULL, sd, 8);
        float4 q4 = __ldg(reinterpret_cast<const float4*>(&q[(size_t)s * 128 + 4 * lane]));
        float4 k4 = __ldg(reinterpret_cast<const float4*>(&k[(size_t)d * 128 + 4 * lane]));

        #pragma unroll 1
        for (int it = 0; it < 8; it++) {
            // prefetch next iteration's gathers
            int sn = 0, dn = 0;
            float4 qn, kn;
            if (it < 7) {
                sn = __shfl_sync(FULL, sd, it + 1);
                dn = __shfl_sync(FULL, sd, it + 9);
                qn = __ldg(reinterpret_cast<const float4*>(&q[(size_t)sn * 128 + 4 * lane]));
                kn = __ldg(reinterpret_cast<const float4*>(&k[(size_t)dn * 128 + 4 * lane]));
            }
            float4 v4 = __ldg(reinterpret_cast<const float4*>(&v[(size_t)s * 128 + 4 * lane]));

            int row = wid * 8 + it;
            float pd = q4.x * k4.x + q4.y * k4.y + q4.z * k4.z + q4.w * k4.w;
            pd += __shfl_xor_sync(FULL, pd, 1);
            pd += __shfl_xor_sync(FULL, pd, 2);
            pd += __shfl_xor_sync(FULL, pd, 4);

            float4 m4 = *reinterpret_cast<const float4*>(&P[row * 132 + 4 * lane]);
            m4.x = fmaf(pd, INV_SCALE, m4.x);
            m4.y = fmaf(pd, INV_SCALE, m4.y);
            m4.z = fmaf(pd, INV_SCALE, m4.z);
            m4.w = fmaf(pd, INV_SCALE, m4.w);

            // softmax over the 4 heads: partners at lane^8, lane^16
            float4 mx = m4;
            #pragma unroll
            for (int off = 8; off <= 16; off <<= 1) {
                mx.x = fmaxf(mx.x, __shfl_xor_sync(FULL, mx.x, off));
                mx.y = fmaxf(mx.y, __shfl_xor_sync(FULL, mx.y, off));
                mx.z = fmaxf(mx.z, __shfl_xor_sync(FULL, mx.z, off));
                mx.w = fmaxf(mx.w, __shfl_xor_sync(FULL, mx.w, off));
            }
            float4 ex;
            ex.x = __expf(m4.x - mx.x); ex.y = __expf(m4.y - mx.y);
            ex.z = __expf(m4.z - mx.z); ex.w = __expf(m4.w - mx.w);
            float4 sx = ex;
            #pragma unroll
            for (int off = 8; off <= 16; off <<= 1) {
                sx.x += __shfl_xor_sync(FULL, sx.x, off);
                sx.y += __shfl_xor_sync(FULL, sx.y, off);
                sx.z += __shfl_xor_sync(FULL, sx.z, off);
                sx.w += __shfl_xor_sync(FULL, sx.w, off);
            }
            float4 msg;
            msg.x = v4.x * ex.x / sx.x;
            msg.y = v4.y * ex.y / sx.y;
            msg.z = v4.z * ex.z / sx.z;
            msg.w = v4.w * ex.w / sx.w;
            float* ap = &agg[(size_t)d * 128 + 4 * lane];
            asm volatile("red.global.add.v4.f32 [%0], {%1, %2, %3, %4};"
                         :: "l"(ap), "f"(msg.x), "f"(msg.y), "f"(msg.z), "f"(msg.w)
                         : "memory");

            // layernorm over 128 cols
            float ls = m4.x + m4.y + m4.z + m4.w;
            float lq = m4.x * m4.x + m4.y * m4.y + m4.z * m4.z + m4.w * m4.w;
            #pragma unroll
            for (int off = 16; off > 0; off >>= 1) {
                ls += __shfl_xor_sync(FULL, ls, off);
                lq += __shfl_xor_sync(FULL, lq, off);
            }
            float mu = ls * (1.0f / 128.0f);
            float var = lq * (1.0f / 128.0f) - mu * mu;
            float rs = rsqrtf(var + LN_EPS);

            float4 sil;
            {
                float t0 = fmaf((m4.x - mu) * rs, ge.x, gb.x);
                float t1 = fmaf((m4.y - mu) * rs, ge.y, gb.y);
                float t2f = fmaf((m4.z - mu) * rs, ge.z, gb.z);
                float t3 = fmaf((m4.w - mu) * rs, ge.w, gb.w);
                sil.x = t0 / (1.0f + __expf(-t0));
                sil.y = t1 / (1.0f + __expf(-t1));
                sil.z = t2f / (1.0f + __expf(-t2f));
                sil.w = t3 / (1.0f + __expf(-t3));
            }
            *reinterpret_cast<float4*>(&P[row * 132 + 4 * lane]) = sil;

            s = sn; d = dn; q4 = qn; k4 = kn;
        }
    }
    __syncthreads();

    // Phase C: y = eres + bev + silu   (warps wn>=2 hold the Wev product)
    if (wn >= 2) {
        #pragma unroll
        for (int i = 0; i < 2; i++) {
            int rlo = wm * 32 + i * 16 + g;
            int rhi = rlo + 8;
            #pragma unroll
            for (int j = 0; j < 8; j++) {
                int colw = (wn & 1) * 64 + j * 8 + t2;
                float2 o0, o1;
                o0.x = acc[i][j][0] + bb[j].x + P[rlo * 132 + colw];
                o0.y = acc[i][j][1] + bb[j].y + P[rlo * 132 + colw + 1];
                o1.x = acc[i][j][2] + bb[j].x + P[rhi * 132 + colw];
                o1.y = acc[i][j][3] + bb[j].y + P[rhi * 132 + colw + 1];
                *reinterpret_cast<float2*>(&y_out[(size_t)(e0 + rlo) * 128 + colw]) = o0;
                *reinterpret_cast<float2*>(&y_out[(size_t)(e0 + rhi) * 128 + colw]) = o1;
            }
        }
    }
}

// ---------------------------------------------------------------------------
// Node finalize: x = node_res + silu(LN_128(agg)), float4 lanes
// ---------------------------------------------------------------------------
__global__ __launch_bounds__(256) void node_kernel(
    const float* __restrict__ agg, const float* __restrict__ nres,
    const float* __restrict__ ln_ng, const float* __restrict__ ln_nb,
    float* __restrict__ x_out)
{
    int node = (blockIdx.x * blockDim.x + threadIdx.x) >> 5;
    int lane = threadIdx.x & 31;
    if (node >= NN) return;
    const unsigned FULL = 0xffffffffu;

    size_t base = (size_t)node * 128 + 4 * lane;
    float4 a = __ldg(reinterpret_cast<const float4*>(&agg[base]));

    float ls = a.x + a.y + a.z + a.w;
    float lq = a.x * a.x + a.y * a.y + a.z * a.z + a.w * a.w;
    #pragma unroll
    for (int off = 16; off > 0; off >>= 1) {
        ls += __shfl_xor_sync(FULL, ls, off);
        lq += __shfl_xor_sync(FULL, lq, off);
    }
    float mu  = ls * (1.0f / 128.0f);
    float var = lq * (1.0f / 128.0f) - mu * mu;
    float rs  = rsqrtf(var + LN_EPS);

    float4 g = __ldg(reinterpret_cast<const float4*>(&ln_ng[4 * lane]));
    float4 b = __ldg(reinterpret_cast<const float4*>(&ln_nb[4 * lane]));
    float4 r = __ldg(reinterpret_cast<const float4*>(&nres[base]));

    float t0 = fmaf((a.x - mu) * rs, g.x, b.x);
    float t1 = fmaf((a.y - mu) * rs, g.y, b.y);
    float t2 = fmaf((a.z - mu) * rs, g.z, b.z);
    float t3 = fmaf((a.w - mu) * rs, g.w, b.w);
    float4 o;
    o.x = t0 / (1.0f + __expf(-t0)) + r.x;
    o.y = t1 / (1.0f + __expf(-t1)) + r.y;
    o.z = t2 / (1.0f + __expf(-t2)) + r.z;
    o.w = t3 / (1.0f + __expf(-t3)) + r.w;
    *reinterpret_cast<float4*>(&x_out[base]) = o;
}

// ---------------------------------------------------------------------------
// Launch
// ---------------------------------------------------------------------------
extern "C" void kernel_launch(void* const* d_in, const int* in_sizes, int n_in,
                              void* d_out, int out_size)
{
    const float* node_feats = (const float*)d_in[0];
    const float* edge_feats = (const float*)d_in[1];
    const int*   src        = (const int*)d_in[2];
    const int*   dst        = (const int*)d_in[3];
    const float* Wq   = (const float*)d_in[4];
    const float* bq   = (const float*)d_in[5];
    const float* Wk   = (const float*)d_in[6];
    const float* bk   = (const float*)d_in[7];
    const float* Wv   = (const float*)d_in[8];
    const float* bv   = (const float*)d_in[9];
    const float* We   = (const float*)d_in[10];
    const float* be   = (const float*)d_in[11];
    const float* Wev  = (const float*)d_in[12];
    const float* bev  = (const float*)d_in[13];
    const float* Wout = (const float*)d_in[14];
    const float* bout = (const float*)d_in[15];
    const float* ln_ng = (const float*)d_in[16];
    const float* ln_nb = (const float*)d_in[17];
    const float* ln_eg = (const float*)d_in[18];
    const float* ln_eb = (const float*)d_in[19];

    float* scratch = nullptr;
    cudaGetSymbolAddress((void**)&scratch, g_scratch);
    float* q    = scratch;
    float* kk   = q    + (size_t)NN * 128;
    float* vv   = kk   + (size_t)NN * 128;
    float* nres = vv   + (size_t)NN * 128;
    float* agg  = nres + (size_t)NN * 128;

    float* x_out = (float*)d_out;
    float* y_out = x_out + (size_t)NN * 128;

    static bool attr_set = false;
    if (!attr_set) {
        cudaFuncSetAttribute(gemm_node, cudaFuncAttributeMaxDynamicSharedMemorySize, SMEM_GEMM);
        cudaFuncSetAttribute(edge_fused, cudaFuncAttributeMaxDynamicSharedMemorySize, SMEM_EDGE);
        attr_set = true;
    }

    // g_wbf order: 0=Wq 1=Wk 2=Wv 3=Wout 4=We 5=Wev
    prep_w<<<6, 256>>>(Wq, Wk, Wv, Wout, We, Wev);

    // node GEMMs (782 blocks) + agg zeroing (391 blocks), one launch
    gemm_node<<<2 * NBLK + ZBLK, 512, SMEM_GEMM>>>(
        node_feats, bq, bk, bv, bout, q, kk, vv, nres, agg);

    edge_fused<<<EE / 128, 512, SMEM_EDGE>>>(
        edge_feats, be, bev, src, dst, q, kk, vv, ln_eg, ln_eb, agg, y_out);

    node_kernel<<<NN / 8, 256>>>(agg, nres, ln_ng, ln_nb, x_out);
}